// round 1
// baseline (speedup 1.0000x reference)
#include <cuda_runtime.h>
#include <math.h>

// ---------------------------------------------------------------------------
// GRAPEIso: conv3x3(3->1024) + pixel_shuffle(4) + pixel_unshuffle(2) + head
// algebraically folded into a 96-output 3x3 conv, then Gaussian splatting
// with exclusive shared-memory image tiles (no global atomics).
//
// Fixed shapes (from setup_inputs): B=4, inp 3x128x128, scale=2,
// grid 256x256 gaussians/batch, image 4x3x256x256 fp32 output.
// ---------------------------------------------------------------------------

#define BATCH   4
#define INH     128
#define INW     128
#define GH      256
#define GW      256
#define IMH     256
#define IMW     256
#define NGAUSS  (GH * GW)

#define TW      32      // image tile width
#define TH      32      // image tile height
#define RS      40      // gaussian gather span per tile dim: [t0-3, t0+36]

// Scratch (allocation-free contract: __device__ globals)
__device__ float  g_weff[4 * 27 * 24];          // [uv][t][o], o contiguous
__device__ float  g_beff[4 * 24];               // [uv][o]
__device__ float2 g_center[BATCH * NGAUSS];     // (cx, cy)
__device__ float4 g_color [BATCH * NGAUSS];     // (r, g, b, pad)

// ---------------------------------------------------------------------------
// Kernel 0: fold conv weights + head into effective 3x3 conv weights.
// W_eff[o,u,v,t] = sum_{c,a,e} w_head[o, c*4+a*2+e] * w_enc[c*16+(2u+a)*4+(2v+e), t]
// B_eff[o,u,v]   = b_head[o] + sum_{c,a,e} w_head[o, c*4+a*2+e] * b_enc[...]
// ---------------------------------------------------------------------------
__global__ void __launch_bounds__(672) fold_kernel(
    const float* __restrict__ w_enc,   // (1024, 3, 3, 3) -> [C*27 + t]
    const float* __restrict__ b_enc,   // (1024,)
    const float* __restrict__ w_head,  // (24, 256)
    const float* __restrict__ b_head)  // (24,)
{
    int uv = blockIdx.x;               // 0..3
    int u = uv >> 1, v = uv & 1;
    int tid = threadIdx.x;

    if (tid < 648) {
        int t = tid / 24;              // 0..26  (ic*9 + ky*3 + kx)
        int o = tid - t * 24;          // 0..23
        float acc = 0.f;
        #pragma unroll 4
        for (int c = 0; c < 64; c++) {
            #pragma unroll
            for (int a = 0; a < 2; a++) {
                #pragma unroll
                for (int e = 0; e < 2; e++) {
                    int ch = c * 4 + a * 2 + e;
                    int C  = c * 16 + (2 * u + a) * 4 + (2 * v + e);
                    acc += w_head[o * 256 + ch] * w_enc[C * 27 + t];
                }
            }
        }
        g_weff[uv * 648 + t * 24 + o] = acc;
    } else if (tid < 672) {
        int o = tid - 648;             // 0..23
        float acc = b_head[o];
        #pragma unroll 4
        for (int ch = 0; ch < 256; ch++) {
            int c = ch >> 2, a = (ch >> 1) & 1, e = ch & 1;
            int C = c * 16 + (2 * u + a) * 4 + (2 * v + e);
            acc += w_head[o * 256 + ch] * b_enc[C];
        }
        g_beff[uv * 24 + o] = acc;
    }
}

// ---------------------------------------------------------------------------
// Kernel 1: per input position (b,i,j), compute 4 sub-pixel predictions
// (24 values each) via the folded weights, then softmax/tanh combine into
// per-gaussian center + color records.
// ---------------------------------------------------------------------------
__global__ void __launch_bounds__(256) predict_kernel(const float* __restrict__ inp)
{
    __shared__ float sW[4 * 648];      // [uv][t][o]
    __shared__ float sB[4 * 24];

    for (int i = threadIdx.x; i < 4 * 648; i += 256) sW[i] = g_weff[i];
    if (threadIdx.x < 96) sB[threadIdx.x] = g_beff[threadIdx.x];
    __syncthreads();

    int idx = blockIdx.x * 256 + threadIdx.x;   // 0..65535
    int b   = idx >> 14;
    int rem = idx & 16383;
    int i   = rem >> 7;
    int j   = rem & 127;

    // Load 3x3x3 input patch with zero padding (SAME conv)
    float patch[27];
    const float* ib = inp + (size_t)b * 3 * INH * INW;
    #pragma unroll
    for (int ic = 0; ic < 3; ic++) {
        #pragma unroll
        for (int ky = 0; ky < 3; ky++) {
            int y = i + ky - 1;
            #pragma unroll
            for (int kx = 0; kx < 3; kx++) {
                int x = j + kx - 1;
                float vv = 0.f;
                if ((unsigned)y < INH && (unsigned)x < INW)
                    vv = __ldg(ib + ic * INH * INW + y * INW + x);
                patch[ic * 9 + ky * 3 + kx] = vv;
            }
        }
    }

    #pragma unroll
    for (int uv = 0; uv < 4; uv++) {
        float acc[24];
        #pragma unroll
        for (int o = 0; o < 24; o++) acc[o] = sB[uv * 24 + o];

        const float4* wrow = (const float4*)(sW + uv * 648);
        #pragma unroll
        for (int t = 0; t < 27; t++) {
            float xv = patch[t];
            #pragma unroll
            for (int q = 0; q < 6; q++) {
                float4 wv = wrow[t * 6 + q];
                acc[q * 4 + 0] = fmaf(wv.x, xv, acc[q * 4 + 0]);
                acc[q * 4 + 1] = fmaf(wv.y, xv, acc[q * 4 + 1]);
                acc[q * 4 + 2] = fmaf(wv.z, xv, acc[q * 4 + 2]);
                acc[q * 4 + 3] = fmaf(wv.w, xv, acc[q * 4 + 3]);
            }
        }

        // acc[k*6 + d]: d=0..2 rgb, d=3..4 off, d=5 logit ; K=4
        float lg0 = acc[5], lg1 = acc[11], lg2 = acc[17], lg3 = acc[23];
        float m = fmaxf(fmaxf(lg0, lg1), fmaxf(lg2, lg3));
        float w0 = __expf(lg0 - m), w1 = __expf(lg1 - m);
        float w2 = __expf(lg2 - m), w3 = __expf(lg3 - m);
        float inv = 1.f / (w0 + w1 + w2 + w3);

        float r = 0.f, g = 0.f, bl = 0.f, ox = 0.f, oy = 0.f;
        #pragma unroll
        for (int k = 0; k < 4; k++) {
            float wk = ((k == 0) ? w0 : (k == 1) ? w1 : (k == 2) ? w2 : w3) * inv;
            r  = fmaf(acc[k * 6 + 0], wk, r);
            g  = fmaf(acc[k * 6 + 1], wk, g);
            bl = fmaf(acc[k * 6 + 2], wk, bl);
            ox = fmaf(tanhf(acc[k * 6 + 3]), wk, ox);
            oy = fmaf(tanhf(acc[k * 6 + 4]), wk, oy);
        }

        int u = uv >> 1, v = uv & 1;
        int gy = 2 * i + u, gx = 2 * j + v;
        // cx = xi + 2*off_x - 1 ; cy = yi + 2*off_y - 1   (derived in closed form)
        float cx = (float)gx + 2.f * ox - 1.f;
        float cy = (float)gy + 2.f * oy - 1.f;

        int gidx = b * NGAUSS + gy * GW + gx;
        g_center[gidx] = make_float2(cx, cy);
        g_color[gidx]  = make_float4(r, g, bl, 0.f);
    }
}

// ---------------------------------------------------------------------------
// Kernel 2: rasterize. One CTA per exclusive 32x32 image tile per batch.
// Gather gaussians from grid region [t0-3, t0+36] (covers worst-case
// footprint [xi-5, xi+3]); accumulate in shared memory (ATOMS, no REDG);
// clip and store coalesced.
// s_px = 0.5 => power = -2*(dx^2+dy^2); exp is separable per axis.
// ---------------------------------------------------------------------------
__global__ void __launch_bounds__(256) raster_kernel(float* __restrict__ out)
{
    __shared__ float acc[3 * TH * TW];  // plane layout [ch][ty][tx]

    int tx0 = blockIdx.x * TW;
    int ty0 = blockIdx.y * TH;
    int b   = blockIdx.z;

    for (int p = threadIdx.x; p < 3 * TH * TW; p += 256) acc[p] = 0.f;
    __syncthreads();

    const float2* ctr = g_center + b * NGAUSS;
    const float4* col = g_color  + b * NGAUSS;

    for (int idx = threadIdx.x; idx < RS * RS; idx += 256) {
        int ry = idx / RS;
        int rx = idx - ry * RS;
        int gy = ty0 - 3 + ry;
        int gx = tx0 - 3 + rx;
        if ((unsigned)gy >= GH || (unsigned)gx >= GW) continue;

        int gi = gy * GW + gx;
        float2 c    = ctr[gi];
        float4 rgbv = col[gi];

        float ixf = floorf(c.x);
        float iyf = floorf(c.y);
        float ex[5], ey[5];
        #pragma unroll
        for (int o = 0; o < 5; o++) {
            float dx = ixf + (float)(o - 2) - c.x;
            float dy = iyf + (float)(o - 2) - c.y;
            ex[o] = __expf(-2.f * dx * dx);
            ey[o] = __expf(-2.f * dy * dy);
        }
        int ix = (int)ixf;
        int iy = (int)iyf;

        #pragma unroll
        for (int oy = 0; oy < 5; oy++) {
            int ty = iy - 2 + oy - ty0;
            if ((unsigned)ty >= TH) continue;
            float eyv = ey[oy];
            #pragma unroll
            for (int ox = 0; ox < 5; ox++) {
                int tx = ix - 2 + ox - tx0;
                if ((unsigned)tx >= TW) continue;
                float a = fminf(eyv * ex[ox], 0.999f);
                if (a > (1.0f / 255.0f)) {
                    int p = ty * TW + tx;
                    atomicAdd(&acc[p],               a * rgbv.x);
                    atomicAdd(&acc[TH * TW + p],     a * rgbv.y);
                    atomicAdd(&acc[2 * TH * TW + p], a * rgbv.z);
                }
            }
        }
    }
    __syncthreads();

    float* ob = out + (size_t)b * 3 * IMH * IMW;
    for (int p = threadIdx.x; p < TH * TW; p += 256) {
        int ty = p >> 5;          // TW = 32
        int tx = p & 31;
        int o  = (ty0 + ty) * IMW + (tx0 + tx);
        #pragma unroll
        for (int ch = 0; ch < 3; ch++) {
            float vv = acc[ch * TH * TW + p];
            ob[ch * IMH * IMW + o] = fminf(fmaxf(vv, 0.f), 1.f);
        }
    }
}

// ---------------------------------------------------------------------------
// Launch: fold -> predict -> raster, all graph-capturable, no allocs/syncs.
// Inputs (metadata order): inp, w_enc, b_enc, w_head, b_head, scale(unused)
// ---------------------------------------------------------------------------
extern "C" void kernel_launch(void* const* d_in, const int* in_sizes, int n_in,
                              void* d_out, int out_size)
{
    const float* inp    = (const float*)d_in[0];
    const float* w_enc  = (const float*)d_in[1];
    const float* b_enc  = (const float*)d_in[2];
    const float* w_head = (const float*)d_in[3];
    const float* b_head = (const float*)d_in[4];
    float* out = (float*)d_out;

    fold_kernel<<<4, 672>>>(w_enc, b_enc, w_head, b_head);
    predict_kernel<<<256, 256>>>(inp);

    dim3 g(IMW / TW, IMH / TH, BATCH);
    raster_kernel<<<g, 256>>>(out);
}

// round 2
// speedup vs baseline: 1.9010x; 1.9010x over previous
#include <cuda_runtime.h>
#include <math.h>

// ---------------------------------------------------------------------------
// GRAPEIso: conv3x3(3->1024) + pixel_shuffle(4) + pixel_unshuffle(2) + head
// algebraically folded into a 96-output 3x3 conv, then Gaussian splatting
// with exclusive shared-memory image tiles (no global atomics).
//
// Fixed shapes: B=4, inp 3x128x128, scale=2, grid 256x256 gaussians/batch,
// image 4x3x256x256 fp32 output.
// ---------------------------------------------------------------------------

#define BATCH   4
#define INH     128
#define INW     128
#define GH      256
#define GW      256
#define IMH     256
#define IMW     256
#define NGAUSS  (GH * GW)

#define TW      32      // image tile width
#define TH      32      // image tile height
#define RS      40      // gaussian gather span per tile dim: [t0-3, t0+36]

// Scratch (allocation-free contract: __device__ globals)
__device__ float  g_weff[4 * 27 * 24];          // [uv][t][o], o contiguous
__device__ float  g_beff[4 * 24];               // [uv][o]
__device__ float2 g_center[BATCH * NGAUSS];     // (cx, cy)
__device__ float4 g_color [BATCH * NGAUSS];     // (r, g, b, pad)

// ---------------------------------------------------------------------------
// Kernel 0: fold conv weights + head into effective 3x3 conv weights.
// W_eff[o,uv,t] = sum_ch w_head[o,ch] * w_enc[C(ch,uv), t]
// Two 128-channel passes, both operands staged in shared memory.
// One thread per output element (648 weights + 24 biases per uv).
// ---------------------------------------------------------------------------
#define FOLD_THREADS 672
__global__ void __launch_bounds__(FOLD_THREADS) fold_kernel(
    const float* __restrict__ w_enc,   // (1024, 3, 3, 3) -> [C*27 + t]
    const float* __restrict__ b_enc,   // (1024,)
    const float* __restrict__ w_head,  // (24, 256)
    const float* __restrict__ b_head)  // (24,)
{
    __shared__ float sH[128 * 24];     // [ch'][o]  (transposed w_head half)
    __shared__ float sE[128 * 27];     // [ch'][t]  (w_enc slice half)
    __shared__ float sBE[128];         // b_enc slice half

    int uv = blockIdx.x;               // 0..3
    int u = uv >> 1, v = uv & 1;
    int tid = threadIdx.x;
    int t = tid / 24;                  // 0..26 for tid<648
    int o = tid - t * 24;              // 0..23

    float acc  = 0.f;
    float accB = (tid < 24) ? b_head[tid] : 0.f;

    #pragma unroll
    for (int p = 0; p < 2; p++) {
        // stage w_head half, transposed: sH[ch*24 + o] = w_head[o*256 + p*128 + ch]
        for (int i = tid; i < 128 * 24; i += FOLD_THREADS) {
            int oo = i >> 7, ch = i & 127;          // coalesced global read
            sH[ch * 24 + oo] = w_head[oo * 256 + p * 128 + ch];
        }
        // stage w_enc slice half: sE[ch*27 + t] = w_enc[C(ch)*27 + t]
        for (int i = tid; i < 128 * 27; i += FOLD_THREADS) {
            int ch = i / 27, tt = i - ch * 27;
            int chg = p * 128 + ch;
            int c = chg >> 2, a = (chg >> 1) & 1, e = chg & 1;
            int C = c * 16 + (2 * u + a) * 4 + (2 * v + e);
            sE[ch * 27 + tt] = w_enc[C * 27 + tt];
        }
        if (tid < 128) {
            int chg = p * 128 + tid;
            int c = chg >> 2, a = (chg >> 1) & 1, e = chg & 1;
            int C = c * 16 + (2 * u + a) * 4 + (2 * v + e);
            sBE[tid] = b_enc[C];
        }
        __syncthreads();

        if (tid < 648) {
            #pragma unroll 8
            for (int ch = 0; ch < 128; ch++)
                acc = fmaf(sH[ch * 24 + o], sE[ch * 27 + t], acc);
        }
        if (tid < 24) {
            #pragma unroll 8
            for (int ch = 0; ch < 128; ch++)
                accB = fmaf(sH[ch * 24 + tid], sBE[ch], accB);
        }
        __syncthreads();
    }

    if (tid < 648) g_weff[uv * 648 + t * 24 + o] = acc;
    if (tid < 24)  g_beff[uv * 24 + tid] = accB;
}

// ---------------------------------------------------------------------------
// Kernel 1: per input position (b,i,j), compute 4 sub-pixel predictions
// (24 values each) via the folded weights, then softmax/tanh combine into
// per-gaussian center + color records.
// ---------------------------------------------------------------------------
__global__ void __launch_bounds__(256) predict_kernel(const float* __restrict__ inp)
{
    __shared__ float sW[4 * 648];      // [uv][t][o]
    __shared__ float sB[4 * 24];

    for (int i = threadIdx.x; i < 4 * 648; i += 256) sW[i] = g_weff[i];
    if (threadIdx.x < 96) sB[threadIdx.x] = g_beff[threadIdx.x];
    __syncthreads();

    int idx = blockIdx.x * 256 + threadIdx.x;   // 0..65535
    int b   = idx >> 14;
    int rem = idx & 16383;
    int i   = rem >> 7;
    int j   = rem & 127;

    // Load 3x3x3 input patch with zero padding (SAME conv)
    float patch[27];
    const float* ib = inp + (size_t)b * 3 * INH * INW;
    #pragma unroll
    for (int ic = 0; ic < 3; ic++) {
        #pragma unroll
        for (int ky = 0; ky < 3; ky++) {
            int y = i + ky - 1;
            #pragma unroll
            for (int kx = 0; kx < 3; kx++) {
                int x = j + kx - 1;
                float vv = 0.f;
                if ((unsigned)y < INH && (unsigned)x < INW)
                    vv = __ldg(ib + ic * INH * INW + y * INW + x);
                patch[ic * 9 + ky * 3 + kx] = vv;
            }
        }
    }

    #pragma unroll
    for (int uv = 0; uv < 4; uv++) {
        float acc[24];
        #pragma unroll
        for (int o = 0; o < 24; o++) acc[o] = sB[uv * 24 + o];

        const float4* wrow = (const float4*)(sW + uv * 648);
        #pragma unroll
        for (int t = 0; t < 27; t++) {
            float xv = patch[t];
            #pragma unroll
            for (int q = 0; q < 6; q++) {
                float4 wv = wrow[t * 6 + q];
                acc[q * 4 + 0] = fmaf(wv.x, xv, acc[q * 4 + 0]);
                acc[q * 4 + 1] = fmaf(wv.y, xv, acc[q * 4 + 1]);
                acc[q * 4 + 2] = fmaf(wv.z, xv, acc[q * 4 + 2]);
                acc[q * 4 + 3] = fmaf(wv.w, xv, acc[q * 4 + 3]);
            }
        }

        // acc[k*6 + d]: d=0..2 rgb, d=3..4 off, d=5 logit ; K=4
        float lg0 = acc[5], lg1 = acc[11], lg2 = acc[17], lg3 = acc[23];
        float m = fmaxf(fmaxf(lg0, lg1), fmaxf(lg2, lg3));
        float w0 = __expf(lg0 - m), w1 = __expf(lg1 - m);
        float w2 = __expf(lg2 - m), w3 = __expf(lg3 - m);
        float inv = 1.f / (w0 + w1 + w2 + w3);

        float r = 0.f, g = 0.f, bl = 0.f, ox = 0.f, oy = 0.f;
        #pragma unroll
        for (int k = 0; k < 4; k++) {
            float wk = ((k == 0) ? w0 : (k == 1) ? w1 : (k == 2) ? w2 : w3) * inv;
            r  = fmaf(acc[k * 6 + 0], wk, r);
            g  = fmaf(acc[k * 6 + 1], wk, g);
            bl = fmaf(acc[k * 6 + 2], wk, bl);
            ox = fmaf(tanhf(acc[k * 6 + 3]), wk, ox);
            oy = fmaf(tanhf(acc[k * 6 + 4]), wk, oy);
        }

        int u = uv >> 1, v = uv & 1;
        int gy = 2 * i + u, gx = 2 * j + v;
        float cx = (float)gx + 2.f * ox - 1.f;
        float cy = (float)gy + 2.f * oy - 1.f;

        int gidx = b * NGAUSS + gy * GW + gx;
        g_center[gidx] = make_float2(cx, cy);
        g_color[gidx]  = make_float4(r, g, bl, 0.f);
    }
}

// ---------------------------------------------------------------------------
// Kernel 2: rasterize. One CTA per exclusive 32x32 image tile per batch.
// Gather gaussians from grid region [t0-3, t0+36]; accumulate in shared
// memory; clip and store coalesced.
// Within each 40-wide gather row, lanes process columns in stride-8 order
// (rx = (j%5)*8 + j/5) so adjacent lanes' 5x5 footprints are disjoint ->
// spread-address ATOMS instead of same-address serialization.
// s_px = 0.5 => power = -2*(dx^2+dy^2); exp separable per axis.
// ---------------------------------------------------------------------------
__global__ void __launch_bounds__(256) raster_kernel(float* __restrict__ out)
{
    __shared__ float acc[3 * TH * TW];  // plane layout [ch][ty][tx]

    int tx0 = blockIdx.x * TW;
    int ty0 = blockIdx.y * TH;
    int b   = blockIdx.z;

    for (int p = threadIdx.x; p < 3 * TH * TW; p += 256) acc[p] = 0.f;
    __syncthreads();

    const float2* ctr = g_center + b * NGAUSS;
    const float4* col = g_color  + b * NGAUSS;

    for (int idx = threadIdx.x; idx < RS * RS; idx += 256) {
        int ry = idx / RS;
        int j  = idx - ry * RS;
        int rx = (j % 5) * 8 + (j / 5);     // de-conflict permutation
        int gy = ty0 - 3 + ry;
        int gx = tx0 - 3 + rx;
        if ((unsigned)gy >= GH || (unsigned)gx >= GW) continue;

        int gi = gy * GW + gx;
        float2 c    = ctr[gi];
        float4 rgbv = col[gi];

        float ixf = floorf(c.x);
        float iyf = floorf(c.y);
        float ex[5], ey[5];
        #pragma unroll
        for (int o = 0; o < 5; o++) {
            float dx = ixf + (float)(o - 2) - c.x;
            float dy = iyf + (float)(o - 2) - c.y;
            ex[o] = __expf(-2.f * dx * dx);
            ey[o] = __expf(-2.f * dy * dy);
        }
        int ix = (int)ixf;
        int iy = (int)iyf;

        #pragma unroll
        for (int oy = 0; oy < 5; oy++) {
            int ty = iy - 2 + oy - ty0;
            if ((unsigned)ty >= TH) continue;
            float eyv = ey[oy];
            #pragma unroll
            for (int ox = 0; ox < 5; ox++) {
                int tx = ix - 2 + ox - tx0;
                if ((unsigned)tx >= TW) continue;
                float a = fminf(eyv * ex[ox], 0.999f);
                if (a > (1.0f / 255.0f)) {
                    int p = ty * TW + tx;
                    atomicAdd(&acc[p],               a * rgbv.x);
                    atomicAdd(&acc[TH * TW + p],     a * rgbv.y);
                    atomicAdd(&acc[2 * TH * TW + p], a * rgbv.z);
                }
            }
        }
    }
    __syncthreads();

    float* ob = out + (size_t)b * 3 * IMH * IMW;
    for (int p = threadIdx.x; p < TH * TW; p += 256) {
        int ty = p >> 5;          // TW = 32
        int tx = p & 31;
        int o  = (ty0 + ty) * IMW + (tx0 + tx);
        #pragma unroll
        for (int ch = 0; ch < 3; ch++) {
            float vv = acc[ch * TH * TW + p];
            ob[ch * IMH * IMW + o] = fminf(fmaxf(vv, 0.f), 1.f);
        }
    }
}

// ---------------------------------------------------------------------------
// Launch: fold -> predict -> raster, all graph-capturable, no allocs/syncs.
// Inputs (metadata order): inp, w_enc, b_enc, w_head, b_head, scale(unused)
// ---------------------------------------------------------------------------
extern "C" void kernel_launch(void* const* d_in, const int* in_sizes, int n_in,
                              void* d_out, int out_size)
{
    const float* inp    = (const float*)d_in[0];
    const float* w_enc  = (const float*)d_in[1];
    const float* b_enc  = (const float*)d_in[2];
    const float* w_head = (const float*)d_in[3];
    const float* b_head = (const float*)d_in[4];
    float* out = (float*)d_out;

    fold_kernel<<<4, FOLD_THREADS>>>(w_enc, b_enc, w_head, b_head);
    predict_kernel<<<256, 256>>>(inp);

    dim3 g(IMW / TW, IMH / TH, BATCH);
    raster_kernel<<<g, 256>>>(out);
}

// round 3
// speedup vs baseline: 2.2103x; 1.1627x over previous
#include <cuda_runtime.h>
#include <math.h>

// ---------------------------------------------------------------------------
// GRAPEIso: conv3x3(3->1024) + pixel_shuffle(4) + pixel_unshuffle(2) + head
// algebraically folded into a 96-output 3x3 conv, then Gaussian splatting
// with exclusive shared-memory image tiles (no global atomics).
//
// Fixed shapes: B=4, inp 3x128x128, scale=2, grid 256x256 gaussians/batch,
// image 4x3x256x256 fp32 output.
// ---------------------------------------------------------------------------

#define BATCH   4
#define INH     128
#define INW     128
#define GH      256
#define GW      256
#define IMH     256
#define IMW     256
#define NGAUSS  (GH * GW)

#define TW      32      // image tile width
#define TH      32      // image tile height
#define RS      40      // gaussian gather span per tile dim: [t0-3, t0+36]

typedef unsigned long long ull;

#define FMA_F32X2(acc, a, b) \
    asm("fma.rn.f32x2 %0, %1, %2, %0;" : "+l"(acc) : "l"(a), "l"(b))
#define PACK_F32X2(out, lo, hi) \
    asm("mov.b64 %0, {%1, %2};" : "=l"(out) : "f"(lo), "f"(hi))
#define UNPACK_F32X2(lo, hi, in) \
    asm("mov.b64 {%0, %1}, %2;" : "=f"(lo), "=f"(hi) : "l"(in))

// Scratch (allocation-free contract: __device__ globals)
__device__ float  g_weff[4 * 27 * 24];          // [uv][t][o], o contiguous
__device__ float  g_beff[4 * 24];               // [uv][o]
__device__ float2 g_center[BATCH * NGAUSS];     // (cx, cy)
__device__ float4 g_color [BATCH * NGAUSS];     // (r, g, b, pad)

// ---------------------------------------------------------------------------
// Kernel 0: fold conv weights + head into effective 3x3 conv weights.
// One WARP per output element: 2592 weights + 96 biases = 2688 warps.
// Each lane accumulates 8 of the 256 channels, then shfl-reduce.
// ---------------------------------------------------------------------------
__global__ void __launch_bounds__(128) fold_kernel(
    const float* __restrict__ w_enc,   // (1024, 3, 3, 3) -> [C*27 + t]
    const float* __restrict__ b_enc,   // (1024,)
    const float* __restrict__ w_head,  // (24, 256)
    const float* __restrict__ b_head)  // (24,)
{
    int w    = blockIdx.x * 4 + (threadIdx.x >> 5);
    int lane = threadIdx.x & 31;

    if (w < 2592) {
        int uv = w / 648;
        int r  = w - uv * 648;
        int t  = r / 24;
        int o  = r - t * 24;
        int u = uv >> 1, v = uv & 1;

        float acc = 0.f;
        #pragma unroll
        for (int k = 0; k < 8; k++) {
            int ch = k * 32 + lane;
            int c = ch >> 2, a = (ch >> 1) & 1, e = ch & 1;
            int C = c * 16 + (2 * u + a) * 4 + (2 * v + e);
            acc = fmaf(__ldg(w_head + o * 256 + ch), __ldg(w_enc + C * 27 + t), acc);
        }
        #pragma unroll
        for (int s = 16; s; s >>= 1) acc += __shfl_xor_sync(~0u, acc, s);
        if (lane == 0) g_weff[uv * 648 + t * 24 + o] = acc;
    } else if (w < 2688) {
        int idx = w - 2592;
        int uv  = idx / 24;
        int o   = idx - uv * 24;
        int u = uv >> 1, v = uv & 1;

        float acc = 0.f;
        #pragma unroll
        for (int k = 0; k < 8; k++) {
            int ch = k * 32 + lane;
            int c = ch >> 2, a = (ch >> 1) & 1, e = ch & 1;
            int C = c * 16 + (2 * u + a) * 4 + (2 * v + e);
            acc = fmaf(__ldg(w_head + o * 256 + ch), __ldg(b_enc + C), acc);
        }
        #pragma unroll
        for (int s = 16; s; s >>= 1) acc += __shfl_xor_sync(~0u, acc, s);
        if (lane == 0) g_beff[uv * 24 + o] = b_head[o] + acc;
    }
}

// ---------------------------------------------------------------------------
// Kernel 1: per input position (b,i,j), compute 4 sub-pixel predictions
// (24 values each) via the folded weights (packed f32x2 FMA), then
// softmax/tanh combine into per-gaussian center + color records.
// ---------------------------------------------------------------------------
__global__ void __launch_bounds__(256) predict_kernel(const float* __restrict__ inp)
{
    __shared__ __align__(16) float sW[4 * 648];      // [uv][t][o]
    __shared__ __align__(16) float sB[4 * 24];

    for (int i = threadIdx.x; i < 4 * 648; i += 256) sW[i] = g_weff[i];
    if (threadIdx.x < 96) sB[threadIdx.x] = g_beff[threadIdx.x];
    __syncthreads();

    int idx = blockIdx.x * 256 + threadIdx.x;   // 0..65535
    int b   = idx >> 14;
    int rem = idx & 16383;
    int i   = rem >> 7;
    int j   = rem & 127;

    // Load 3x3x3 input patch with zero padding (SAME conv)
    float patch[27];
    const float* ib = inp + (size_t)b * 3 * INH * INW;
    #pragma unroll
    for (int ic = 0; ic < 3; ic++) {
        #pragma unroll
        for (int ky = 0; ky < 3; ky++) {
            int y = i + ky - 1;
            #pragma unroll
            for (int kx = 0; kx < 3; kx++) {
                int x = j + kx - 1;
                float vv = 0.f;
                if ((unsigned)y < INH && (unsigned)x < INW)
                    vv = __ldg(ib + ic * INH * INW + y * INW + x);
                patch[ic * 9 + ky * 3 + kx] = vv;
            }
        }
    }

    // Pre-pack patch values as (x,x) f32x2 once
    ull patch2[27];
    #pragma unroll
    for (int t = 0; t < 27; t++) PACK_F32X2(patch2[t], patch[t], patch[t]);

    #pragma unroll
    for (int uv = 0; uv < 4; uv++) {
        // 24 accumulators as 12 packed f32x2
        ull acc2[12];
        #pragma unroll
        for (int q = 0; q < 12; q++)
            PACK_F32X2(acc2[q], sB[uv * 24 + 2 * q], sB[uv * 24 + 2 * q + 1]);

        const ulonglong2* wrow = (const ulonglong2*)(sW + uv * 648);
        #pragma unroll
        for (int t = 0; t < 27; t++) {
            ull xv2 = patch2[t];
            #pragma unroll
            for (int q = 0; q < 6; q++) {
                ulonglong2 w2 = wrow[t * 6 + q];   // 4 weights (2 f32x2)
                FMA_F32X2(acc2[2 * q],     w2.x, xv2);
                FMA_F32X2(acc2[2 * q + 1], w2.y, xv2);
            }
        }

        float acc[24];
        #pragma unroll
        for (int q = 0; q < 12; q++)
            UNPACK_F32X2(acc[2 * q], acc[2 * q + 1], acc2[q]);

        // acc[k*6 + d]: d=0..2 rgb, d=3..4 off, d=5 logit ; K=4
        float lg0 = acc[5], lg1 = acc[11], lg2 = acc[17], lg3 = acc[23];
        float m = fmaxf(fmaxf(lg0, lg1), fmaxf(lg2, lg3));
        float w0 = __expf(lg0 - m), w1 = __expf(lg1 - m);
        float w2 = __expf(lg2 - m), w3 = __expf(lg3 - m);
        float inv = 1.f / (w0 + w1 + w2 + w3);

        float r = 0.f, g = 0.f, bl = 0.f, ox = 0.f, oy = 0.f;
        #pragma unroll
        for (int k = 0; k < 4; k++) {
            float wk = ((k == 0) ? w0 : (k == 1) ? w1 : (k == 2) ? w2 : w3) * inv;
            r  = fmaf(acc[k * 6 + 0], wk, r);
            g  = fmaf(acc[k * 6 + 1], wk, g);
            bl = fmaf(acc[k * 6 + 2], wk, bl);
            ox = fmaf(tanhf(acc[k * 6 + 3]), wk, ox);
            oy = fmaf(tanhf(acc[k * 6 + 4]), wk, oy);
        }

        int u = uv >> 1, v = uv & 1;
        int gy = 2 * i + u, gx = 2 * j + v;
        float cx = (float)gx + 2.f * ox - 1.f;
        float cy = (float)gy + 2.f * oy - 1.f;

        int gidx = b * NGAUSS + gy * GW + gx;
        g_center[gidx] = make_float2(cx, cy);
        g_color[gidx]  = make_float4(r, g, bl, 0.f);
    }
}

// ---------------------------------------------------------------------------
// Kernel 2: rasterize. One CTA per exclusive 32x32 image tile per batch.
// Gather gaussians from grid region [t0-3, t0+36]; accumulate in shared
// memory; clip and store coalesced.
// Within each 40-wide gather row, lanes process columns in stride-8 order
// (rx = (j%5)*8 + j/5) so adjacent lanes' 5x5 footprints are disjoint.
// s_px = 0.5 => power = -2*(dx^2+dy^2); exp separable per axis.
// ---------------------------------------------------------------------------
__global__ void __launch_bounds__(256) raster_kernel(float* __restrict__ out)
{
    __shared__ float acc[3 * TH * TW];  // plane layout [ch][ty][tx]

    int tx0 = blockIdx.x * TW;
    int ty0 = blockIdx.y * TH;
    int b   = blockIdx.z;

    for (int p = threadIdx.x; p < 3 * TH * TW; p += 256) acc[p] = 0.f;
    __syncthreads();

    const float2* ctr = g_center + b * NGAUSS;
    const float4* col = g_color  + b * NGAUSS;

    for (int idx = threadIdx.x; idx < RS * RS; idx += 256) {
        int ry = idx / RS;
        int j  = idx - ry * RS;
        int rx = (j % 5) * 8 + (j / 5);     // de-conflict permutation
        int gy = ty0 - 3 + ry;
        int gx = tx0 - 3 + rx;
        if ((unsigned)gy >= GH || (unsigned)gx >= GW) continue;

        int gi = gy * GW + gx;
        float2 c = ctr[gi];

        float ixf = floorf(c.x);
        float iyf = floorf(c.y);
        int ix = (int)ixf;
        int iy = (int)iyf;

        // bbox reject before any MUFU work: footprint [i-2, i+2] vs tile
        int txl = ix - 2 - tx0;
        int tyl = iy - 2 - ty0;
        if (txl >= TW || txl <= -5 || tyl >= TH || tyl <= -5) continue;

        float4 rgbv = col[gi];

        float ex[5], ey[5];
        #pragma unroll
        for (int o = 0; o < 5; o++) {
            float dx = ixf + (float)(o - 2) - c.x;
            float dy = iyf + (float)(o - 2) - c.y;
            ex[o] = __expf(-2.f * dx * dx);
            ey[o] = __expf(-2.f * dy * dy);
        }

        #pragma unroll
        for (int oy = 0; oy < 5; oy++) {
            int ty = tyl + oy;
            if ((unsigned)ty >= TH) continue;
            float eyv = ey[oy];
            #pragma unroll
            for (int ox = 0; ox < 5; ox++) {
                int tx = txl + ox;
                if ((unsigned)tx >= TW) continue;
                float a = fminf(eyv * ex[ox], 0.999f);
                if (a > (1.0f / 255.0f)) {
                    int p = ty * TW + tx;
                    atomicAdd(&acc[p],               a * rgbv.x);
                    atomicAdd(&acc[TH * TW + p],     a * rgbv.y);
                    atomicAdd(&acc[2 * TH * TW + p], a * rgbv.z);
                }
            }
        }
    }
    __syncthreads();

    float* ob = out + (size_t)b * 3 * IMH * IMW;
    for (int p = threadIdx.x; p < TH * TW; p += 256) {
        int ty = p >> 5;          // TW = 32
        int tx = p & 31;
        int o  = (ty0 + ty) * IMW + (tx0 + tx);
        #pragma unroll
        for (int ch = 0; ch < 3; ch++) {
            float vv = acc[ch * TH * TW + p];
            ob[ch * IMH * IMW + o] = fminf(fmaxf(vv, 0.f), 1.f);
        }
    }
}

// ---------------------------------------------------------------------------
// Launch: fold -> predict -> raster, all graph-capturable, no allocs/syncs.
// Inputs (metadata order): inp, w_enc, b_enc, w_head, b_head, scale(unused)
// ---------------------------------------------------------------------------
extern "C" void kernel_launch(void* const* d_in, const int* in_sizes, int n_in,
                              void* d_out, int out_size)
{
    const float* inp    = (const float*)d_in[0];
    const float* w_enc  = (const float*)d_in[1];
    const float* b_enc  = (const float*)d_in[2];
    const float* w_head = (const float*)d_in[3];
    const float* b_head = (const float*)d_in[4];
    float* out = (float*)d_out;

    fold_kernel<<<672, 128>>>(w_enc, b_enc, w_head, b_head);
    predict_kernel<<<256, 256>>>(inp);

    dim3 g(IMW / TW, IMH / TH, BATCH);
    raster_kernel<<<g, 256>>>(out);
}

// round 4
// speedup vs baseline: 3.0818x; 1.3943x over previous
#include <cuda_runtime.h>
#include <math.h>

// ---------------------------------------------------------------------------
// GRAPEIso: conv3x3(3->1024) + pixel_shuffle(4) + pixel_unshuffle(2) + head
// algebraically folded into a 96-output 3x3 conv, then Gaussian splatting
// with exclusive shared-memory image tiles (no global atomics).
//
// Fixed shapes: B=4, inp 3x128x128, scale=2, grid 256x256 gaussians/batch,
// image 4x3x256x256 fp32 output.
// ---------------------------------------------------------------------------

#define BATCH   4
#define INH     128
#define INW     128
#define GH      256
#define GW      256
#define IMH     256
#define IMW     256
#define NGAUSS  (GH * GW)

// Raster tiling: 16x16 image tile per CTA -> 16*16*4 = 1024 CTAs (balanced
// on 148 SMs: 6.92 avg vs 7 max). Gather halo 22x22 (4x4 effective footprint).
#define TW      16
#define TH      16
#define RSX     22      // gx in [tx0-2, tx0+19]
#define RSY     22      // gy in [ty0-2, ty0+19]

// Scratch (allocation-free contract: __device__ globals)
__device__ float  g_weff[4 * 27 * 24];          // [uv][t][o], o contiguous
__device__ float  g_beff[4 * 24];               // [uv][o]
__device__ float2 g_center[BATCH * NGAUSS];     // (cx, cy)
__device__ float4 g_color [BATCH * NGAUSS];     // (r, g, b, pad)

// ---------------------------------------------------------------------------
// Kernel 0: fold conv weights + head into effective 3x3 conv weights.
// One WARP per output element: 2592 weights + 96 biases = 2688 warps.
// ---------------------------------------------------------------------------
__global__ void __launch_bounds__(128) fold_kernel(
    const float* __restrict__ w_enc,   // (1024, 3, 3, 3) -> [C*27 + t]
    const float* __restrict__ b_enc,   // (1024,)
    const float* __restrict__ w_head,  // (24, 256)
    const float* __restrict__ b_head)  // (24,)
{
    int w    = blockIdx.x * 4 + (threadIdx.x >> 5);
    int lane = threadIdx.x & 31;

    if (w < 2592) {
        int uv = w / 648;
        int r  = w - uv * 648;
        int t  = r / 24;
        int o  = r - t * 24;
        int u = uv >> 1, v = uv & 1;

        float acc = 0.f;
        #pragma unroll
        for (int k = 0; k < 8; k++) {
            int ch = k * 32 + lane;
            int c = ch >> 2, a = (ch >> 1) & 1, e = ch & 1;
            int C = c * 16 + (2 * u + a) * 4 + (2 * v + e);
            acc = fmaf(__ldg(w_head + o * 256 + ch), __ldg(w_enc + C * 27 + t), acc);
        }
        #pragma unroll
        for (int s = 16; s; s >>= 1) acc += __shfl_xor_sync(~0u, acc, s);
        if (lane == 0) g_weff[uv * 648 + t * 24 + o] = acc;
    } else if (w < 2688) {
        int idx = w - 2592;
        int uv  = idx / 24;
        int o   = idx - uv * 24;
        int u = uv >> 1, v = uv & 1;

        float acc = 0.f;
        #pragma unroll
        for (int k = 0; k < 8; k++) {
            int ch = k * 32 + lane;
            int c = ch >> 2, a = (ch >> 1) & 1, e = ch & 1;
            int C = c * 16 + (2 * u + a) * 4 + (2 * v + e);
            acc = fmaf(__ldg(w_head + o * 256 + ch), __ldg(b_enc + C), acc);
        }
        #pragma unroll
        for (int s = 16; s; s >>= 1) acc += __shfl_xor_sync(~0u, acc, s);
        if (lane == 0) g_beff[uv * 24 + o] = b_head[o] + acc;
    }
}

// ---------------------------------------------------------------------------
// Kernel 1: per input position (b,i,j), compute 4 sub-pixel predictions
// (24 values each) via the folded weights (scalar FFMA; f32x2 regressed via
// register pressure), then softmax/tanh combine into center/color records.
// 1024 CTAs x 64 threads for SM load balance.
// ---------------------------------------------------------------------------
__global__ void __launch_bounds__(64) predict_kernel(const float* __restrict__ inp)
{
    __shared__ __align__(16) float sW[4 * 648];      // [uv][t][o]
    __shared__ float sB[4 * 24];

    for (int i = threadIdx.x; i < 4 * 648; i += 64) sW[i] = g_weff[i];
    for (int i = threadIdx.x; i < 96; i += 64) sB[i] = g_beff[i];
    __syncthreads();

    int idx = blockIdx.x * 64 + threadIdx.x;    // 0..65535
    int b   = idx >> 14;
    int rem = idx & 16383;
    int i   = rem >> 7;
    int j   = rem & 127;

    // Load 3x3x3 input patch with zero padding (SAME conv)
    float patch[27];
    const float* ib = inp + (size_t)b * 3 * INH * INW;
    #pragma unroll
    for (int ic = 0; ic < 3; ic++) {
        #pragma unroll
        for (int ky = 0; ky < 3; ky++) {
            int y = i + ky - 1;
            #pragma unroll
            for (int kx = 0; kx < 3; kx++) {
                int x = j + kx - 1;
                float vv = 0.f;
                if ((unsigned)y < INH && (unsigned)x < INW)
                    vv = __ldg(ib + ic * INH * INW + y * INW + x);
                patch[ic * 9 + ky * 3 + kx] = vv;
            }
        }
    }

    #pragma unroll
    for (int uv = 0; uv < 4; uv++) {
        float acc[24];
        #pragma unroll
        for (int o = 0; o < 24; o++) acc[o] = sB[uv * 24 + o];

        const float4* wrow = (const float4*)(sW + uv * 648);
        #pragma unroll
        for (int t = 0; t < 27; t++) {
            float xv = patch[t];
            #pragma unroll
            for (int q = 0; q < 6; q++) {
                float4 wv = wrow[t * 6 + q];
                acc[q * 4 + 0] = fmaf(wv.x, xv, acc[q * 4 + 0]);
                acc[q * 4 + 1] = fmaf(wv.y, xv, acc[q * 4 + 1]);
                acc[q * 4 + 2] = fmaf(wv.z, xv, acc[q * 4 + 2]);
                acc[q * 4 + 3] = fmaf(wv.w, xv, acc[q * 4 + 3]);
            }
        }

        // acc[k*6 + d]: d=0..2 rgb, d=3..4 off, d=5 logit ; K=4
        float lg0 = acc[5], lg1 = acc[11], lg2 = acc[17], lg3 = acc[23];
        float m = fmaxf(fmaxf(lg0, lg1), fmaxf(lg2, lg3));
        float w0 = __expf(lg0 - m), w1 = __expf(lg1 - m);
        float w2 = __expf(lg2 - m), w3 = __expf(lg3 - m);
        float inv = 1.f / (w0 + w1 + w2 + w3);

        float r = 0.f, g = 0.f, bl = 0.f, ox = 0.f, oy = 0.f;
        #pragma unroll
        for (int k = 0; k < 4; k++) {
            float wk = ((k == 0) ? w0 : (k == 1) ? w1 : (k == 2) ? w2 : w3) * inv;
            r  = fmaf(acc[k * 6 + 0], wk, r);
            g  = fmaf(acc[k * 6 + 1], wk, g);
            bl = fmaf(acc[k * 6 + 2], wk, bl);
            ox = fmaf(tanhf(acc[k * 6 + 3]), wk, ox);
            oy = fmaf(tanhf(acc[k * 6 + 4]), wk, oy);
        }

        int u = uv >> 1, v = uv & 1;
        int gy = 2 * i + u, gx = 2 * j + v;
        float cx = (float)gx + 2.f * ox - 1.f;
        float cy = (float)gy + 2.f * oy - 1.f;

        int gidx = b * NGAUSS + gy * GW + gx;
        g_center[gidx] = make_float2(cx, cy);
        g_color[gidx]  = make_float4(r, g, bl, 0.f);
    }
}

// ---------------------------------------------------------------------------
// Kernel 2: rasterize. One CTA per exclusive 16x16 image tile per batch
// (1024 CTAs). The reference's alpha cutoff (1/255) provably kills the
// d=-2 row/col of the 5x5 window (|d|>=2 -> alpha <= e^-8 < 1/255), so the
// effective footprint is 4x4 at offsets d in {-1,0,1,2} around floor(c):
// 16 positions, 8 expf. Gather halo is 22x22. Lanes take columns in
// (j*5 mod 22) order so adjacent lanes' 4-wide footprints are disjoint.
// ---------------------------------------------------------------------------
__global__ void __launch_bounds__(256) raster_kernel(float* __restrict__ out)
{
    __shared__ float acc[3 * TH * TW];  // plane layout [ch][ty][tx]

    int tx0 = (blockIdx.x & 15) * TW;
    int ty0 = (blockIdx.x >> 4) * TH;
    int b   = blockIdx.y;

    for (int p = threadIdx.x; p < 3 * TH * TW; p += 256) acc[p] = 0.f;
    __syncthreads();

    const float2* ctr = g_center + b * NGAUSS;
    const float4* col = g_color  + b * NGAUSS;

    for (int idx = threadIdx.x; idx < RSX * RSY; idx += 256) {
        int ry = idx / RSX;
        int j  = idx - ry * RSX;
        int rx = (j * 5) % RSX;             // de-conflict permutation
        int gy = ty0 - 2 + ry;
        int gx = tx0 - 2 + rx;
        if ((unsigned)gy >= GH || (unsigned)gx >= GW) continue;

        int gi = gy * GW + gx;
        float2 c = ctr[gi];

        float ixf = floorf(c.x);
        float iyf = floorf(c.y);

        // effective footprint: [ix-1, ix+2] x [iy-1, iy+2]
        int txl = (int)ixf - 1 - tx0;
        int tyl = (int)iyf - 1 - ty0;
        if (txl >= TW || txl <= -4 || tyl >= TH || tyl <= -4) continue;

        float4 rgbv = col[gi];

        float ex[4], ey[4];
        #pragma unroll
        for (int o = 0; o < 4; o++) {
            float dx = ixf + (float)(o - 1) - c.x;
            float dy = iyf + (float)(o - 1) - c.y;
            ex[o] = __expf(-2.f * dx * dx);
            ey[o] = __expf(-2.f * dy * dy);
        }

        #pragma unroll
        for (int oy = 0; oy < 4; oy++) {
            int ty = tyl + oy;
            if ((unsigned)ty >= TH) continue;
            float eyv = ey[oy];
            #pragma unroll
            for (int ox = 0; ox < 4; ox++) {
                int tx = txl + ox;
                if ((unsigned)tx >= TW) continue;
                float a = fminf(eyv * ex[ox], 0.999f);
                if (a > (1.0f / 255.0f)) {
                    int p = ty * TW + tx;
                    atomicAdd(&acc[p],               a * rgbv.x);
                    atomicAdd(&acc[TH * TW + p],     a * rgbv.y);
                    atomicAdd(&acc[2 * TH * TW + p], a * rgbv.z);
                }
            }
        }
    }
    __syncthreads();

    float* ob = out + (size_t)b * 3 * IMH * IMW;
    for (int p = threadIdx.x; p < TH * TW; p += 256) {
        int ty = p >> 4;          // TW = 16
        int tx = p & 15;
        int o  = (ty0 + ty) * IMW + (tx0 + tx);
        #pragma unroll
        for (int ch = 0; ch < 3; ch++) {
            float vv = acc[ch * TH * TW + p];
            ob[ch * IMH * IMW + o] = fminf(fmaxf(vv, 0.f), 1.f);
        }
    }
}

// ---------------------------------------------------------------------------
// Launch: fold -> predict -> raster, all graph-capturable, no allocs/syncs.
// Inputs (metadata order): inp, w_enc, b_enc, w_head, b_head, scale(unused)
// ---------------------------------------------------------------------------
extern "C" void kernel_launch(void* const* d_in, const int* in_sizes, int n_in,
                              void* d_out, int out_size)
{
    const float* inp    = (const float*)d_in[0];
    const float* w_enc  = (const float*)d_in[1];
    const float* b_enc  = (const float*)d_in[2];
    const float* w_head = (const float*)d_in[3];
    const float* b_head = (const float*)d_in[4];
    float* out = (float*)d_out;

    fold_kernel<<<672, 128>>>(w_enc, b_enc, w_head, b_head);
    predict_kernel<<<1024, 64>>>(inp);

    dim3 g(256, BATCH);                 // 16x16 tiles -> (16*16, B)
    raster_kernel<<<g, 256>>>(out);
}